// round 12
// baseline (speedup 1.0000x reference)
#include <cuda_runtime.h>
#include <cuda_bf16.h>
#include <cstdint>
#include <math.h>

// Problem dims
#define B_ 2
#define T_ 256
#define N_ 128
#define F_ 16
#define D_ 128
#define H_ 288
#define E_ 1024
#define M_TOTAL (B_*T_*N_)

typedef uint32_t u32;

// Scratch (allocation-free)
__device__ float g_S1[(size_t)M_TOTAL * H_];
__device__ float g_R1[(size_t)M_TOTAL * H_];
__device__ float g_pet2[2][256 * H_];     // [0]=petS(t), [1]=petR(t)+bc1
__device__ int   g_se_s[E_], g_re_s[E_], g_perm[E_];

// Fragment-ordered split-bf16 weight images.
#define OFF_EMB 0
#define OFF_W1  1024
#define OFF_W2  9216
#define OFF_WC  17408
#define WF_TOTAL 35840
__device__ u32 g_Wf[2][2][WF_TOTAL];

// ---------------- helpers ---------------------------------------------------
__device__ __forceinline__ u32 bpack(__nv_bfloat16 a, __nv_bfloat16 b) {
    return ((u32)__bfloat16_as_ushort(b) << 16) | (u32)__bfloat16_as_ushort(a);
}
__device__ __forceinline__ u32 split_pack(float v0, float v1, u32& lo) {
    __nv_bfloat16 h0 = __float2bfloat16(v0);
    __nv_bfloat16 h1 = __float2bfloat16(v1);
    lo = bpack(__float2bfloat16(v0 - __bfloat162float(h0)),
               __float2bfloat16(v1 - __bfloat162float(h1)));
    return bpack(h0, h1);
}
__device__ __forceinline__ void mma16816(float* d, const u32* a, u32 b0, u32 b1) {
    asm volatile(
        "mma.sync.aligned.m16n8k16.row.col.f32.bf16.bf16.f32 "
        "{%0,%1,%2,%3}, {%4,%5,%6,%7}, {%8,%9}, {%0,%1,%2,%3};"
        : "+f"(d[0]), "+f"(d[1]), "+f"(d[2]), "+f"(d[3])
        : "r"(a[0]), "r"(a[1]), "r"(a[2]), "r"(a[3]), "r"(b0), "r"(b1));
}

// ---------------------------------------------------------------------------
// prep_wf (unchanged)
// ---------------------------------------------------------------------------
__global__ void prep_wf(const float* __restrict__ W_emb,
                        const float* __restrict__ Ws1, const float* __restrict__ Ws2,
                        const float* __restrict__ Wr1, const float* __restrict__ Wr2,
                        const float* __restrict__ Wc1)
{
    const int chain = blockIdx.y;
    int pos = blockIdx.x * 256 + threadIdx.x;
    if (pos >= WF_TOTAL) return;

    const float* W; int rel, NJ, N = 128, koff = 0, coff = 0;
    if (pos < OFF_W1)      { rel = pos;          NJ = 16; W = W_emb; }
    else if (pos < OFF_W2) { rel = pos - OFF_W1; NJ = 16; W = chain ? Wr1 : Ws1; }
    else if (pos < OFF_WC) { rel = pos - OFF_W2; NJ = 16; W = chain ? Wr2 : Ws2; }
    else {
        int rel2 = pos - OFF_WC;
        int c = rel2 / 6144; rel = rel2 % 6144;
        NJ = 12; W = Wc1; N = 288; koff = chain ? 144 : 0; coff = 96 * c;
    }
    int r    = rel & 1;
    int lane = (rel >> 1) & 31;
    int t    = rel >> 6;
    int j    = t % NJ;
    int kt   = t / NJ;
    int gg   = lane >> 2;
    int tg   = lane & 3;
    int k    = kt * 16 + r * 8 + 2 * tg;
    int n    = coff + 8 * j + gg;

    float v0 = W[(size_t)(k + koff) * N + n];
    float v1 = W[(size_t)(k + 1 + koff) * N + n];
    u32 lo;
    u32 hi = split_pack(v0, v1, lo);
    g_Wf[chain][0][pos] = hi;
    g_Wf[chain][1][pos] = lo;
}

// ---------------------------------------------------------------------------
// pet2_kernel (unchanged)
// ---------------------------------------------------------------------------
__global__ void pet2_kernel(const float* __restrict__ Wc1,
                            const float* __restrict__ bc1)
{
    const int t = blockIdx.x;       // 0..255
    const int c = threadIdx.x;      // 0..287

    __shared__ float sv[2][8];
    if (c < 8) {
        double dv = exp((double)(2 * c) * (-log(10000.0) / 16.0));
        double a = (double)t * dv;
        sv[0][c] = (float)sin(a);
        sv[1][c] = (float)cos(a);
    }
    __syncthreads();

    float accS = 0.f, accR = bc1[c];
    #pragma unroll
    for (int i = 0; i < 8; i++) {
        accS = fmaf(sv[0][i], Wc1[(128 + 2 * i) * H_ + c], accS);
        accS = fmaf(sv[1][i], Wc1[(129 + 2 * i) * H_ + c], accS);
        accR = fmaf(sv[0][i], Wc1[(272 + 2 * i) * H_ + c], accR);
        accR = fmaf(sv[1][i], Wc1[(273 + 2 * i) * H_ + c], accR);
    }
    g_pet2[0][t * H_ + c] = accS;
    g_pet2[1][t * H_ + c] = accR;
}

// ---------------------------------------------------------------------------
// sort_edges (unchanged)
// ---------------------------------------------------------------------------
__global__ void sort_edges(const int* __restrict__ se, const int* __restrict__ re)
{
    __shared__ int cnt[129];
    __shared__ int cur[128];
    const int tid = threadIdx.x;    // 256 threads
    if (tid < 129) cnt[tid] = 0;
    __syncthreads();
    for (int e = tid; e < E_; e += 256) atomicAdd(&cnt[se[e] + 1], 1);
    __syncthreads();
    if (tid == 0)
        for (int i = 1; i <= 128; i++) cnt[i] += cnt[i - 1];
    __syncthreads();
    if (tid < 128) cur[tid] = cnt[tid];
    __syncthreads();
    for (int e = tid; e < E_; e += 256) {
        int s = se[e];
        int pos = atomicAdd(&cur[s], 1);
        g_se_s[pos] = s;
        g_re_s[pos] = re[e];
        g_perm[pos] = e;
    }
}

// ---------------------------------------------------------------------------
// layer128: kt-loop NOT unrolled (limits ptxas load-hoisting reg pressure);
// j-loop unrolled (16 independent accumulator chains + 32 independent LDGs).
// ---------------------------------------------------------------------------
__device__ __forceinline__ void layer128(float d[16][4],
                                         u32 Ah[8][4], u32 Al[8][4],
                                         const u32* __restrict__ Whi,
                                         const u32* __restrict__ Wlo,
                                         int seg, const float* __restrict__ bias,
                                         int lane, int tig)
{
    #pragma unroll
    for (int j = 0; j < 16; j++) { d[j][0]=0.f; d[j][1]=0.f; d[j][2]=0.f; d[j][3]=0.f; }
    const uint2* bhp = (const uint2*)(Whi + seg);
    const uint2* blp = (const uint2*)(Wlo + seg);
    #pragma unroll 1
    for (int kt = 0; kt < 8; kt++) {
        #pragma unroll
        for (int j = 0; j < 16; j++) {
            uint2 bh = __ldg(bhp + (kt * 16 + j) * 32 + lane);
            uint2 bl = __ldg(blp + (kt * 16 + j) * 32 + lane);
            mma16816(d[j], Ah[kt], bh.x, bh.y);
            mma16816(d[j], Al[kt], bh.x, bh.y);
            mma16816(d[j], Ah[kt], bl.x, bl.y);
        }
    }
    #pragma unroll
    for (int kt = 0; kt < 8; kt++) {
        float2 bA = *(const float2*)(bias + kt * 16 + 2 * tig);
        float2 bB = *(const float2*)(bias + kt * 16 + 8 + 2 * tig);
        float p0 = fmaxf(d[2*kt][0] + bA.x, 0.f), p1 = fmaxf(d[2*kt][1] + bA.y, 0.f);
        float p2 = fmaxf(d[2*kt][2] + bA.x, 0.f), p3 = fmaxf(d[2*kt][3] + bA.y, 0.f);
        float q0 = fmaxf(d[2*kt+1][0] + bB.x, 0.f), q1 = fmaxf(d[2*kt+1][1] + bB.y, 0.f);
        float q2 = fmaxf(d[2*kt+1][2] + bB.x, 0.f), q3 = fmaxf(d[2*kt+1][3] + bB.y, 0.f);
        Ah[kt][0] = split_pack(p0, p1, Al[kt][0]);
        Ah[kt][1] = split_pack(p2, p3, Al[kt][1]);
        Ah[kt][2] = split_pack(q0, q1, Al[kt][2]);
        Ah[kt][3] = split_pack(q2, q3, Al[kt][3]);
    }
}

// ---------------------------------------------------------------------------
// chain_mma: register-resident chain; 3 CTAs/SM target via launch_bounds.
// ---------------------------------------------------------------------------
__global__ __launch_bounds__(128, 3)
void chain_mma(const float* __restrict__ spikes,
               const float* __restrict__ b_emb,
               const float* __restrict__ bs1, const float* __restrict__ bs2,
               const float* __restrict__ br1, const float* __restrict__ br2)
{
    const int chain = blockIdx.y;
    const int warp  = threadIdx.x >> 5;
    const int lane  = threadIdx.x & 31;
    const int g     = lane >> 2;
    const int tig   = lane & 3;
    const int r0    = blockIdx.x * 64 + warp * 16 + g;

    const u32* Whi = g_Wf[chain][0];
    const u32* Wlo = g_Wf[chain][1];
    const float* b1 = chain ? br1 : bs1;
    const float* b2 = chain ? br2 : bs2;
    float* Out = chain ? g_R1 : g_S1;
    const float* padd = g_pet2[chain] + ((r0 >> 7) & 255) * H_;

    u32 Ah[8][4], Al[8][4];
    float d[16][4];

    {
        const float* sp = spikes + (size_t)r0 * F_;
        float2 v0 = *(const float2*)(sp + 2 * tig);
        float2 v1 = *(const float2*)(sp + 8 * F_ + 2 * tig);
        float2 v2 = *(const float2*)(sp + 2 * tig + 8);
        float2 v3 = *(const float2*)(sp + 8 * F_ + 2 * tig + 8);
        Ah[0][0] = split_pack(v0.x, v0.y, Al[0][0]);
        Ah[0][1] = split_pack(v1.x, v1.y, Al[0][1]);
        Ah[0][2] = split_pack(v2.x, v2.y, Al[0][2]);
        Ah[0][3] = split_pack(v3.x, v3.y, Al[0][3]);

        #pragma unroll
        for (int j = 0; j < 16; j++) { d[j][0]=0.f; d[j][1]=0.f; d[j][2]=0.f; d[j][3]=0.f; }
        const uint2* bhp = (const uint2*)(Whi + OFF_EMB);
        const uint2* blp = (const uint2*)(Wlo + OFF_EMB);
        #pragma unroll
        for (int j = 0; j < 16; j++) {
            uint2 bh = __ldg(bhp + j * 32 + lane);
            uint2 bl = __ldg(blp + j * 32 + lane);
            mma16816(d[j], Ah[0], bh.x, bh.y);
            mma16816(d[j], Al[0], bh.x, bh.y);
            mma16816(d[j], Ah[0], bl.x, bl.y);
        }
        #pragma unroll
        for (int kt = 0; kt < 8; kt++) {
            float2 bA = *(const float2*)(b_emb + kt * 16 + 2 * tig);
            float2 bB = *(const float2*)(b_emb + kt * 16 + 8 + 2 * tig);
            float p0 = d[2*kt][0] + bA.x, p1 = d[2*kt][1] + bA.y;
            float p2 = d[2*kt][2] + bA.x, p3 = d[2*kt][3] + bA.y;
            float q0 = d[2*kt+1][0] + bB.x, q1 = d[2*kt+1][1] + bB.y;
            float q2 = d[2*kt+1][2] + bB.x, q3 = d[2*kt+1][3] + bB.y;
            Ah[kt][0] = split_pack(p0, p1, Al[kt][0]);
            Ah[kt][1] = split_pack(p2, p3, Al[kt][1]);
            Ah[kt][2] = split_pack(q0, q1, Al[kt][2]);
            Ah[kt][3] = split_pack(q2, q3, Al[kt][3]);
        }
    }

    layer128(d, Ah, Al, Whi, Wlo, OFF_W1, b1, lane, tig);
    layer128(d, Ah, Al, Whi, Wlo, OFF_W2, b2, lane, tig);

    #pragma unroll 1
    for (int c = 0; c < 3; c++) {
        float d2[12][4];
        #pragma unroll
        for (int j = 0; j < 12; j++) { d2[j][0]=0.f; d2[j][1]=0.f; d2[j][2]=0.f; d2[j][3]=0.f; }
        const uint2* bhp = (const uint2*)(Whi + OFF_WC + c * 6144);
        const uint2* blp = (const uint2*)(Wlo + OFF_WC + c * 6144);
        #pragma unroll 1
        for (int kt = 0; kt < 8; kt++) {
            #pragma unroll
            for (int j = 0; j < 12; j++) {
                uint2 bh = __ldg(bhp + (kt * 12 + j) * 32 + lane);
                uint2 bl = __ldg(blp + (kt * 12 + j) * 32 + lane);
                mma16816(d2[j], Ah[kt], bh.x, bh.y);
                mma16816(d2[j], Al[kt], bh.x, bh.y);
                mma16816(d2[j], Ah[kt], bl.x, bl.y);
            }
        }
        #pragma unroll
        for (int j = 0; j < 12; j++) {
            int col = c * 96 + j * 8 + 2 * tig;
            float2 pv = *(const float2*)(padd + col);
            *(float2*)(Out + (size_t)r0 * H_ + col) =
                make_float2(d2[j][0] + pv.x, d2[j][1] + pv.y);
            *(float2*)(Out + (size_t)(r0 + 8) * H_ + col) =
                make_float2(d2[j][2] + pv.x, d2[j][3] + pv.y);
        }
    }
}

// ---------------------------------------------------------------------------
// edge_kernel v3 (unchanged — sorted edges, pet folded)
// ---------------------------------------------------------------------------
__global__ __launch_bounds__(256)
void edge_kernel(const float* __restrict__ Wc2, const float* __restrict__ bc2,
                 float* __restrict__ out)
{
    __shared__ float sS[128][33];
    __shared__ float sR[128][33];
    __shared__ float sW[H_ * 5];

    const int t   = blockIdx.x;     // 0..254
    const int b   = blockIdx.y;     // 0..1
    const int tid = threadIdx.x;

    const float* Srow = g_S1 + (size_t)((b * T_ + t + 1) * N_) * H_;
    const float* Rrow = g_R1 + (size_t)((b * T_ + t) * N_) * H_;

    for (int l = tid; l < H_ * 5; l += 256) sW[l] = Wc2[l];

    float bb[5];
    #pragma unroll
    for (int j = 0; j < 5; j++) bb[j] = __ldg(bc2 + j);

    int es[4], er[4], eo[4];
    #pragma unroll
    for (int u = 0; u < 4; u++) {
        int e = u * 256 + tid;
        es[u] = g_se_s[e];
        er[u] = g_re_s[e];
        eo[u] = g_perm[e];
    }
    float acc[4][5] = {};

    #pragma unroll 1
    for (int kc = 0; kc < H_; kc += 32) {
        __syncthreads();
        #pragma unroll
        for (int it = 0; it < 4; it++) {
            int l  = tid + it * 256;
            int n  = l >> 3;
            int k4 = (l & 7) * 4;
            float4 v = *reinterpret_cast<const float4*>(Srow + (size_t)n * H_ + kc + k4);
            sS[n][k4 + 0] = v.x; sS[n][k4 + 1] = v.y;
            sS[n][k4 + 2] = v.z; sS[n][k4 + 3] = v.w;
            float4 u4 = *reinterpret_cast<const float4*>(Rrow + (size_t)n * H_ + kc + k4);
            sR[n][k4 + 0] = u4.x; sR[n][k4 + 1] = u4.y;
            sR[n][k4 + 2] = u4.z; sR[n][k4 + 3] = u4.w;
        }
        __syncthreads();
        #pragma unroll
        for (int kk = 0; kk < 32; kk++) {
            float w0 = sW[(kc + kk) * 5 + 0];
            float w1 = sW[(kc + kk) * 5 + 1];
            float w2 = sW[(kc + kk) * 5 + 2];
            float w3 = sW[(kc + kk) * 5 + 3];
            float w4 = sW[(kc + kk) * 5 + 4];
            #pragma unroll
            for (int u = 0; u < 4; u++) {
                float h = sS[es[u]][kk] + sR[er[u]][kk];
                h = fmaxf(h, 0.f);
                acc[u][0] = fmaf(h, w0, acc[u][0]);
                acc[u][1] = fmaf(h, w1, acc[u][1]);
                acc[u][2] = fmaf(h, w2, acc[u][2]);
                acc[u][3] = fmaf(h, w3, acc[u][3]);
                acc[u][4] = fmaf(h, w4, acc[u][4]);
            }
        }
    }

    #pragma unroll
    for (int u = 0; u < 4; u++) {
        size_t o = ((size_t)(b * 255 + t) * E_ + eo[u]) * 5;
        #pragma unroll
        for (int j = 0; j < 5; j++) out[o + j] = acc[u][j] + bb[j];
    }
}

// ---------------------------------------------------------------------------
extern "C" void kernel_launch(void* const* d_in, const int* in_sizes, int n_in,
                              void* d_out, int out_size)
{
    const float* spikes = (const float*)d_in[0];
    const float* W_emb  = (const float*)d_in[1];
    const float* b_emb  = (const float*)d_in[2];
    const float* Ws1    = (const float*)d_in[3];
    const float* bs1    = (const float*)d_in[4];
    const float* Ws2    = (const float*)d_in[5];
    const float* bs2    = (const float*)d_in[6];
    const float* Wr1    = (const float*)d_in[7];
    const float* br1    = (const float*)d_in[8];
    const float* Wr2    = (const float*)d_in[9];
    const float* br2    = (const float*)d_in[10];
    const float* Wc1    = (const float*)d_in[11];
    const float* bc1    = (const float*)d_in[12];
    const float* Wc2    = (const float*)d_in[13];
    const float* bc2    = (const float*)d_in[14];
    const int*   se     = (const int*)d_in[15];
    const int*   re     = (const int*)d_in[16];
    float* out = (float*)d_out;

    prep_wf<<<dim3((WF_TOTAL + 255) / 256, 2), 256>>>(
        W_emb, Ws1, Ws2, Wr1, Wr2, Wc1);

    pet2_kernel<<<256, H_>>>(Wc1, bc1);

    sort_edges<<<1, 256>>>(se, re);

    chain_mma<<<dim3(M_TOTAL / 64, 2), 128>>>(
        spikes, b_emb, bs1, bs2, br1, br2);

    edge_kernel<<<dim3(255, 2), 256>>>(Wc2, bc2, out);
}

// round 13
// speedup vs baseline: 1.1490x; 1.1490x over previous
#include <cuda_runtime.h>
#include <cuda_bf16.h>
#include <cstdint>
#include <math.h>

// Problem dims
#define B_ 2
#define T_ 256
#define N_ 128
#define F_ 16
#define D_ 128
#define H_ 288
#define E_ 1024
#define M_TOTAL (B_*T_*N_)

typedef uint32_t u32;

// Scratch (allocation-free)
__device__ float g_S1[(size_t)M_TOTAL * H_];
__device__ float g_R1[(size_t)M_TOTAL * H_];
__device__ float g_pet2[2][256 * H_];     // [0]=petS(t), [1]=petR(t)+bc1
__device__ int   g_se_s[E_], g_re_s[E_], g_perm[E_];

// Fragment-ordered split-bf16 weight images.
#define OFF_EMB 0
#define OFF_W1  1024
#define OFF_W2  9216
#define OFF_WC  17408
#define WF_TOTAL 35840
__device__ u32 g_Wf[2][2][WF_TOTAL];

// ---------------- helpers ---------------------------------------------------
__device__ __forceinline__ u32 bpack(__nv_bfloat16 a, __nv_bfloat16 b) {
    return ((u32)__bfloat16_as_ushort(b) << 16) | (u32)__bfloat16_as_ushort(a);
}
__device__ __forceinline__ u32 split_pack(float v0, float v1, u32& lo) {
    __nv_bfloat16 h0 = __float2bfloat16(v0);
    __nv_bfloat16 h1 = __float2bfloat16(v1);
    lo = bpack(__float2bfloat16(v0 - __bfloat162float(h0)),
               __float2bfloat16(v1 - __bfloat162float(h1)));
    return bpack(h0, h1);
}
__device__ __forceinline__ void mma16816(float* d, const u32* a, u32 b0, u32 b1) {
    asm volatile(
        "mma.sync.aligned.m16n8k16.row.col.f32.bf16.bf16.f32 "
        "{%0,%1,%2,%3}, {%4,%5,%6,%7}, {%8,%9}, {%0,%1,%2,%3};"
        : "+f"(d[0]), "+f"(d[1]), "+f"(d[2]), "+f"(d[3])
        : "r"(a[0]), "r"(a[1]), "r"(a[2]), "r"(a[3]), "r"(b0), "r"(b1));
}

// ---------------------------------------------------------------------------
// prep_wf (unchanged)
// ---------------------------------------------------------------------------
__global__ void prep_wf(const float* __restrict__ W_emb,
                        const float* __restrict__ Ws1, const float* __restrict__ Ws2,
                        const float* __restrict__ Wr1, const float* __restrict__ Wr2,
                        const float* __restrict__ Wc1)
{
    const int chain = blockIdx.y;
    int pos = blockIdx.x * 256 + threadIdx.x;
    if (pos >= WF_TOTAL) return;

    const float* W; int rel, NJ, N = 128, koff = 0, coff = 0;
    if (pos < OFF_W1)      { rel = pos;          NJ = 16; W = W_emb; }
    else if (pos < OFF_W2) { rel = pos - OFF_W1; NJ = 16; W = chain ? Wr1 : Ws1; }
    else if (pos < OFF_WC) { rel = pos - OFF_W2; NJ = 16; W = chain ? Wr2 : Ws2; }
    else {
        int rel2 = pos - OFF_WC;
        int c = rel2 / 6144; rel = rel2 % 6144;
        NJ = 12; W = Wc1; N = 288; koff = chain ? 144 : 0; coff = 96 * c;
    }
    int r    = rel & 1;
    int lane = (rel >> 1) & 31;
    int t    = rel >> 6;
    int j    = t % NJ;
    int kt   = t / NJ;
    int gg   = lane >> 2;
    int tg   = lane & 3;
    int k    = kt * 16 + r * 8 + 2 * tg;
    int n    = coff + 8 * j + gg;

    float v0 = W[(size_t)(k + koff) * N + n];
    float v1 = W[(size_t)(k + 1 + koff) * N + n];
    u32 lo;
    u32 hi = split_pack(v0, v1, lo);
    g_Wf[chain][0][pos] = hi;
    g_Wf[chain][1][pos] = lo;
}

// ---------------------------------------------------------------------------
// pet2_kernel (unchanged)
// ---------------------------------------------------------------------------
__global__ void pet2_kernel(const float* __restrict__ Wc1,
                            const float* __restrict__ bc1)
{
    const int t = blockIdx.x;       // 0..255
    const int c = threadIdx.x;      // 0..287

    __shared__ float sv[2][8];
    if (c < 8) {
        double dv = exp((double)(2 * c) * (-log(10000.0) / 16.0));
        double a = (double)t * dv;
        sv[0][c] = (float)sin(a);
        sv[1][c] = (float)cos(a);
    }
    __syncthreads();

    float accS = 0.f, accR = bc1[c];
    #pragma unroll
    for (int i = 0; i < 8; i++) {
        accS = fmaf(sv[0][i], Wc1[(128 + 2 * i) * H_ + c], accS);
        accS = fmaf(sv[1][i], Wc1[(129 + 2 * i) * H_ + c], accS);
        accR = fmaf(sv[0][i], Wc1[(272 + 2 * i) * H_ + c], accR);
        accR = fmaf(sv[1][i], Wc1[(273 + 2 * i) * H_ + c], accR);
    }
    g_pet2[0][t * H_ + c] = accS;
    g_pet2[1][t * H_ + c] = accR;
}

// ---------------------------------------------------------------------------
// sort_edges (unchanged)
// ---------------------------------------------------------------------------
__global__ void sort_edges(const int* __restrict__ se, const int* __restrict__ re)
{
    __shared__ int cnt[129];
    __shared__ int cur[128];
    const int tid = threadIdx.x;    // 256 threads
    if (tid < 129) cnt[tid] = 0;
    __syncthreads();
    for (int e = tid; e < E_; e += 256) atomicAdd(&cnt[se[e] + 1], 1);
    __syncthreads();
    if (tid == 0)
        for (int i = 1; i <= 128; i++) cnt[i] += cnt[i - 1];
    __syncthreads();
    if (tid < 128) cur[tid] = cnt[tid];
    __syncthreads();
    for (int e = tid; e < E_; e += 256) {
        int s = se[e];
        int pos = atomicAdd(&cur[s], 1);
        g_se_s[pos] = s;
        g_re_s[pos] = re[e];
        g_perm[pos] = e;
    }
}

// ---------------------------------------------------------------------------
// layer128_s: full unroll (R11 ILP) with Al frags in SMEM (thread-private,
// conflict-free uint4 slots) to cut register state for 3 CTAs/SM.
// sAl layout: sAl[kt*512 + tid*4 + q]
// ---------------------------------------------------------------------------
__device__ __forceinline__ void layer128_s(float d[16][4],
                                           u32 Ah[8][4], u32* sAl,
                                           const u32* __restrict__ Whi,
                                           const u32* __restrict__ Wlo,
                                           int seg, const float* __restrict__ bias,
                                           int lane, int tig, int tid)
{
    #pragma unroll
    for (int j = 0; j < 16; j++) { d[j][0]=0.f; d[j][1]=0.f; d[j][2]=0.f; d[j][3]=0.f; }
    const uint2* bhp = (const uint2*)(Whi + seg);
    const uint2* blp = (const uint2*)(Wlo + seg);
    #pragma unroll
    for (int kt = 0; kt < 8; kt++) {
        uint4 alv = *(const uint4*)(sAl + kt * 512 + tid * 4);
        u32 Al[4] = {alv.x, alv.y, alv.z, alv.w};
        #pragma unroll
        for (int j = 0; j < 16; j++) {
            uint2 bh = __ldg(bhp + (kt * 16 + j) * 32 + lane);
            uint2 bl = __ldg(blp + (kt * 16 + j) * 32 + lane);
            mma16816(d[j], Ah[kt], bh.x, bh.y);
            mma16816(d[j], Al,     bh.x, bh.y);
            mma16816(d[j], Ah[kt], bl.x, bl.y);
        }
    }
    #pragma unroll
    for (int kt = 0; kt < 8; kt++) {
        float2 bA = *(const float2*)(bias + kt * 16 + 2 * tig);
        float2 bB = *(const float2*)(bias + kt * 16 + 8 + 2 * tig);
        float p0 = fmaxf(d[2*kt][0] + bA.x, 0.f), p1 = fmaxf(d[2*kt][1] + bA.y, 0.f);
        float p2 = fmaxf(d[2*kt][2] + bA.x, 0.f), p3 = fmaxf(d[2*kt][3] + bA.y, 0.f);
        float q0 = fmaxf(d[2*kt+1][0] + bB.x, 0.f), q1 = fmaxf(d[2*kt+1][1] + bB.y, 0.f);
        float q2 = fmaxf(d[2*kt+1][2] + bB.x, 0.f), q3 = fmaxf(d[2*kt+1][3] + bB.y, 0.f);
        uint4 alv;
        Ah[kt][0] = split_pack(p0, p1, alv.x);
        Ah[kt][1] = split_pack(p2, p3, alv.y);
        Ah[kt][2] = split_pack(q0, q1, alv.z);
        Ah[kt][3] = split_pack(q2, q3, alv.w);
        *(uint4*)(sAl + kt * 512 + tid * 4) = alv;
    }
}

// ---------------------------------------------------------------------------
// chain_mma: register-resident chain, Al in smem, 3 CTAs/SM.
// ---------------------------------------------------------------------------
__global__ __launch_bounds__(128, 3)
void chain_mma(const float* __restrict__ spikes,
               const float* __restrict__ b_emb,
               const float* __restrict__ bs1, const float* __restrict__ bs2,
               const float* __restrict__ br1, const float* __restrict__ br2)
{
    __shared__ u32 sAl[8 * 512];    // [kt][tid][q] thread-private Al frags, 16KB

    const int chain = blockIdx.y;
    const int lane  = threadIdx.x & 31;
    const int g     = lane >> 2;
    const int tig   = lane & 3;
    const int tid   = threadIdx.x;
    const int r0    = blockIdx.x * 64 + (tid >> 5) * 16 + g;

    const u32* Whi = g_Wf[chain][0];
    const u32* Wlo = g_Wf[chain][1];
    const float* b1 = chain ? br1 : bs1;
    const float* b2 = chain ? br2 : bs2;
    float* Out = chain ? g_R1 : g_S1;
    const float* padd = g_pet2[chain] + ((r0 >> 7) & 255) * H_;

    u32 Ah[8][4];
    float d[16][4];

    // ---- Layer 0: emb = spikes @ W_emb + b_emb (K=16, 1 k-tile) ----------
    {
        const float* sp = spikes + (size_t)r0 * F_;
        float2 v0 = *(const float2*)(sp + 2 * tig);
        float2 v1 = *(const float2*)(sp + 8 * F_ + 2 * tig);
        float2 v2 = *(const float2*)(sp + 2 * tig + 8);
        float2 v3 = *(const float2*)(sp + 8 * F_ + 2 * tig + 8);
        u32 a0h[4], a0l[4];
        a0h[0] = split_pack(v0.x, v0.y, a0l[0]);
        a0h[1] = split_pack(v1.x, v1.y, a0l[1]);
        a0h[2] = split_pack(v2.x, v2.y, a0l[2]);
        a0h[3] = split_pack(v3.x, v3.y, a0l[3]);

        #pragma unroll
        for (int j = 0; j < 16; j++) { d[j][0]=0.f; d[j][1]=0.f; d[j][2]=0.f; d[j][3]=0.f; }
        const uint2* bhp = (const uint2*)(Whi + OFF_EMB);
        const uint2* blp = (const uint2*)(Wlo + OFF_EMB);
        #pragma unroll
        for (int j = 0; j < 16; j++) {
            uint2 bh = __ldg(bhp + j * 32 + lane);
            uint2 bl = __ldg(blp + j * 32 + lane);
            mma16816(d[j], a0h, bh.x, bh.y);
            mma16816(d[j], a0l, bh.x, bh.y);
            mma16816(d[j], a0h, bl.x, bl.y);
        }
        #pragma unroll
        for (int kt = 0; kt < 8; kt++) {
            float2 bA = *(const float2*)(b_emb + kt * 16 + 2 * tig);
            float2 bB = *(const float2*)(b_emb + kt * 16 + 8 + 2 * tig);
            float p0 = d[2*kt][0] + bA.x, p1 = d[2*kt][1] + bA.y;
            float p2 = d[2*kt][2] + bA.x, p3 = d[2*kt][3] + bA.y;
            float q0 = d[2*kt+1][0] + bB.x, q1 = d[2*kt+1][1] + bB.y;
            float q2 = d[2*kt+1][2] + bB.x, q3 = d[2*kt+1][3] + bB.y;
            uint4 alv;
            Ah[kt][0] = split_pack(p0, p1, alv.x);
            Ah[kt][1] = split_pack(p2, p3, alv.y);
            Ah[kt][2] = split_pack(q0, q1, alv.z);
            Ah[kt][3] = split_pack(q2, q3, alv.w);
            *(uint4*)(sAl + kt * 512 + tid * 4) = alv;
        }
    }

    layer128_s(d, Ah, sAl, Whi, Wlo, OFF_W1, b1, lane, tig, tid);
    layer128_s(d, Ah, sAl, Whi, Wlo, OFF_W2, b2, lane, tig, tid);

    // ---- Layer 3: Out = s @ Wc (N=288, 3 chunks of 96) ---------------------
    #pragma unroll 1
    for (int c = 0; c < 3; c++) {
        float d2[12][4];
        #pragma unroll
        for (int j = 0; j < 12; j++) { d2[j][0]=0.f; d2[j][1]=0.f; d2[j][2]=0.f; d2[j][3]=0.f; }
        const uint2* bhp = (const uint2*)(Whi + OFF_WC + c * 6144);
        const uint2* blp = (const uint2*)(Wlo + OFF_WC + c * 6144);
        #pragma unroll
        for (int kt = 0; kt < 8; kt++) {
            uint4 alv = *(const uint4*)(sAl + kt * 512 + tid * 4);
            u32 Al[4] = {alv.x, alv.y, alv.z, alv.w};
            #pragma unroll
            for (int j = 0; j < 12; j++) {
                uint2 bh = __ldg(bhp + (kt * 12 + j) * 32 + lane);
                uint2 bl = __ldg(blp + (kt * 12 + j) * 32 + lane);
                mma16816(d2[j], Ah[kt], bh.x, bh.y);
                mma16816(d2[j], Al,     bh.x, bh.y);
                mma16816(d2[j], Ah[kt], bl.x, bl.y);
            }
        }
        #pragma unroll
        for (int j = 0; j < 12; j++) {
            int col = c * 96 + j * 8 + 2 * tig;
            float2 pv = *(const float2*)(padd + col);
            *(float2*)(Out + (size_t)r0 * H_ + col) =
                make_float2(d2[j][0] + pv.x, d2[j][1] + pv.y);
            *(float2*)(Out + (size_t)(r0 + 8) * H_ + col) =
                make_float2(d2[j][2] + pv.x, d2[j][3] + pv.y);
        }
    }
}

// ---------------------------------------------------------------------------
// edge_kernel v3 (unchanged — sorted edges, pet folded)
// ---------------------------------------------------------------------------
__global__ __launch_bounds__(256)
void edge_kernel(const float* __restrict__ Wc2, const float* __restrict__ bc2,
                 float* __restrict__ out)
{
    __shared__ float sS[128][33];
    __shared__ float sR[128][33];
    __shared__ float sW[H_ * 5];

    const int t   = blockIdx.x;     // 0..254
    const int b   = blockIdx.y;     // 0..1
    const int tid = threadIdx.x;

    const float* Srow = g_S1 + (size_t)((b * T_ + t + 1) * N_) * H_;
    const float* Rrow = g_R1 + (size_t)((b * T_ + t) * N_) * H_;

    for (int l = tid; l < H_ * 5; l += 256) sW[l] = Wc2[l];

    float bb[5];
    #pragma unroll
    for (int j = 0; j < 5; j++) bb[j] = __ldg(bc2 + j);

    int es[4], er[4], eo[4];
    #pragma unroll
    for (int u = 0; u < 4; u++) {
        int e = u * 256 + tid;
        es[u] = g_se_s[e];
        er[u] = g_re_s[e];
        eo[u] = g_perm[e];
    }
    float acc[4][5] = {};

    #pragma unroll 1
    for (int kc = 0; kc < H_; kc += 32) {
        __syncthreads();
        #pragma unroll
        for (int it = 0; it < 4; it++) {
            int l  = tid + it * 256;
            int n  = l >> 3;
            int k4 = (l & 7) * 4;
            float4 v = *reinterpret_cast<const float4*>(Srow + (size_t)n * H_ + kc + k4);
            sS[n][k4 + 0] = v.x; sS[n][k4 + 1] = v.y;
            sS[n][k4 + 2] = v.z; sS[n][k4 + 3] = v.w;
            float4 u4 = *reinterpret_cast<const float4*>(Rrow + (size_t)n * H_ + kc + k4);
            sR[n][k4 + 0] = u4.x; sR[n][k4 + 1] = u4.y;
            sR[n][k4 + 2] = u4.z; sR[n][k4 + 3] = u4.w;
        }
        __syncthreads();
        #pragma unroll
        for (int kk = 0; kk < 32; kk++) {
            float w0 = sW[(kc + kk) * 5 + 0];
            float w1 = sW[(kc + kk) * 5 + 1];
            float w2 = sW[(kc + kk) * 5 + 2];
            float w3 = sW[(kc + kk) * 5 + 3];
            float w4 = sW[(kc + kk) * 5 + 4];
            #pragma unroll
            for (int u = 0; u < 4; u++) {
                float h = sS[es[u]][kk] + sR[er[u]][kk];
                h = fmaxf(h, 0.f);
                acc[u][0] = fmaf(h, w0, acc[u][0]);
                acc[u][1] = fmaf(h, w1, acc[u][1]);
                acc[u][2] = fmaf(h, w2, acc[u][2]);
                acc[u][3] = fmaf(h, w3, acc[u][3]);
                acc[u][4] = fmaf(h, w4, acc[u][4]);
            }
        }
    }

    #pragma unroll
    for (int u = 0; u < 4; u++) {
        size_t o = ((size_t)(b * 255 + t) * E_ + eo[u]) * 5;
        #pragma unroll
        for (int j = 0; j < 5; j++) out[o + j] = acc[u][j] + bb[j];
    }
}

// ---------------------------------------------------------------------------
extern "C" void kernel_launch(void* const* d_in, const int* in_sizes, int n_in,
                              void* d_out, int out_size)
{
    const float* spikes = (const float*)d_in[0];
    const float* W_emb  = (const float*)d_in[1];
    const float* b_emb  = (const float*)d_in[2];
    const float* Ws1    = (const float*)d_in[3];
    const float* bs1    = (const float*)d_in[4];
    const float* Ws2    = (const float*)d_in[5];
    const float* bs2    = (const float*)d_in[6];
    const float* Wr1    = (const float*)d_in[7];
    const float* br1    = (const float*)d_in[8];
    const float* Wr2    = (const float*)d_in[9];
    const float* br2    = (const float*)d_in[10];
    const float* Wc1    = (const float*)d_in[11];
    const float* bc1    = (const float*)d_in[12];
    const float* Wc2    = (const float*)d_in[13];
    const float* bc2    = (const float*)d_in[14];
    const int*   se     = (const int*)d_in[15];
    const int*   re     = (const int*)d_in[16];
    float* out = (float*)d_out;

    prep_wf<<<dim3((WF_TOTAL + 255) / 256, 2), 256>>>(
        W_emb, Ws1, Ws2, Wr1, Wr2, Wc1);

    pet2_kernel<<<256, H_>>>(Wc1, bc1);

    sort_edges<<<1, 256>>>(se, re);

    chain_mma<<<dim3(M_TOTAL / 64, 2), 128>>>(
        spikes, b_emb, bs1, bs2, br1, br2);

    edge_kernel<<<dim3(255, 2), 256>>>(Wc2, bc2, out);
}